// round 14
// baseline (speedup 1.0000x reference)
#include <cuda_runtime.h>
#include <math.h>
#include <stdint.h>

// Problem constants
#define NB   4
#define CC   256
#define HH   64
#define WW   64
#define HWSZ 4096        // H*W
#define MTOK 16384       // N*H*W tokens
#define GG   8
#define PP   9
#define CG   32          // C/G
#define NOFF 144         // G*P*2
#define NMSK 72          // G*P
#define NCAT 256         // padded off|mask column count

// Scratch (no allocs allowed)
__device__ float g_c1 [MTOK * CC];    // depthwise conv output, NCHW
__device__ float g_xv [MTOK * CC];    // value proj, NHWC
__device__ float g_om [MTOK * NCAT];  // offset(0..143) | mask logits(144..215) | pad
__device__ float g_y  [MTOK * CC];    // sampled output, NHWC
__device__ float g_mu [MTOK];         // LN mean per token
__device__ float g_rs [MTOK];         // LN rsqrt(var+eps) per token

__device__ __forceinline__ float tf32r(float x) {
    uint32_t u;
    asm("cvt.rna.tf32.f32 %0, %1;" : "=r"(u) : "f"(x));
    return __uint_as_float(u);
}

__device__ __forceinline__ float gelu_exact(float v) {
    return 0.5f * v * (1.0f + erff(v * 0.70710678118654752f));
}

__device__ __forceinline__ void mma_tf32(float d[4], const uint32_t a[4], const uint32_t b[2]) {
    asm("mma.sync.aligned.m16n8k8.row.col.f32.tf32.tf32.f32 "
        "{%0,%1,%2,%3}, {%4,%5,%6,%7}, {%8,%9}, {%0,%1,%2,%3};"
        : "+f"(d[0]), "+f"(d[1]), "+f"(d[2]), "+f"(d[3])
        : "r"(a[0]), "r"(a[1]), "r"(a[2]), "r"(a[3]), "r"(b[0]), "r"(b[1]));
}

// concat weight gather: [w_off | w_mask | 0]
__device__ __forceinline__ float catw(const float* __restrict__ w_off,
                                      const float* __restrict__ w_mask,
                                      int k, int col) {
    if (col < NOFF) return w_off[k * NOFF + col];
    if (col < NOFF + NMSK) return w_mask[k * NMSK + (col - NOFF)];
    return 0.f;
}

// ---------------------------------------------------------------------------
// TF32 GEMM body: C[M,256] = A[M,256] @ B[256,256] + bias
// Fragment-friendly permuted smem layout: element i (0..127) of the tile
// dimension is stored at perm(i) = (i&7)*16 + (i>>3); row stride 132 floats.
// -> A fragments: 1 LDS.128 per k-row; B fragments: 2 LDS.128 per k-row.
// ATRANS=0: A row-major [M,K]. ATRANS=1: A from NCHW (per-n column-major).
// ATRANS=2: like 1 but from g_c1 with fused LayerNorm+GELU applied at staging.
// BKIND=0: plain B. BKIND=2: concat [w_off|w_mask|0].
// STORE_NCHW=1: store to NCHW [4][256][4096].
// ---------------------------------------------------------------------------
#define GBM 128
#define GBN 128
#define GBK 16
#define PST 132            // permuted row stride (floats)
#define KTOT 256
#define NKT (KTOT / GBK)
#define SMEM_FLOATS (2 * GBK * PST * 2)   // 8448 floats = 33792 B

template<int ATRANS, int BKIND, int STORE_NCHW>
__device__ __forceinline__ void gemm_body(
    const float* __restrict__ A,
    const float* __restrict__ B0, const float* __restrict__ B1,
    const float* __restrict__ bias0, const float* __restrict__ bias1,
    const float* __restrict__ lng, const float* __restrict__ lnb,
    float* __restrict__ Cout, int bx, int by, float* smem)
{
    float (*As)[GBK][PST] = (float (*)[GBK][PST])smem;
    float (*Bs)[GBK][PST] = (float (*)[GBK][PST])(smem + 2 * GBK * PST);

    int tid  = threadIdx.x;
    int lane = tid & 31;
    int warp = tid >> 5;
    int gid  = lane >> 2;
    int tid4 = lane & 3;
    int wm   = warp >> 1;
    int wn   = warp & 1;
    int m0   = by * GBM;
    int n0   = bx * GBN;

    int ar = tid >> 1;             // ATRANS=0: A row (0..127)
    int ac = (tid & 1) * 8;        // ATRANS=0: A k offset
    int br = tid >> 4;             // k row (0..15)
    int bc = (tid & 15) * 8;       // tile col offset (multiple of 8)
    int bq = bc >> 3;              // = tid & 15

    const float* Aptr;
    if (ATRANS) {
        Aptr = A + (size_t)(m0 >> 12) * CC * HWSZ + (size_t)br * HWSZ + (m0 & 4095) + bc;
    } else {
        Aptr = A + (size_t)(m0 + ar) * KTOT + ac;
    }

    // LN per-column stats (token = m0+bc..+7), invariant over k
    float mu[8], rs[8];
    if (ATRANS == 2) {
        float4 m04 = *(const float4*)(g_mu + m0 + bc);
        float4 m14 = *(const float4*)(g_mu + m0 + bc + 4);
        float4 r04 = *(const float4*)(g_rs + m0 + bc);
        float4 r14 = *(const float4*)(g_rs + m0 + bc + 4);
        mu[0] = m04.x; mu[1] = m04.y; mu[2] = m04.z; mu[3] = m04.w;
        mu[4] = m14.x; mu[5] = m14.y; mu[6] = m14.z; mu[7] = m14.w;
        rs[0] = r04.x; rs[1] = r04.y; rs[2] = r04.z; rs[3] = r04.w;
        rs[4] = r14.x; rs[5] = r14.y; rs[6] = r14.z; rs[7] = r14.w;
    }

    float acc[2][8][4];
    #pragma unroll
    for (int i = 0; i < 2; i++)
        #pragma unroll
        for (int j = 0; j < 8; j++)
            #pragma unroll
            for (int q = 0; q < 4; q++) acc[i][j][q] = 0.f;

    float4 pa0, pa1;
    float pv[8];
    float pgk = 0.f, pbk = 0.f;

    // prologue: k-tile 0
    pa0 = *(const float4*)(Aptr + 0);
    pa1 = *(const float4*)(Aptr + 4);
    if (ATRANS == 2) { pgk = lng[br]; pbk = lnb[br]; }
    if (BKIND == 2) {
        #pragma unroll
        for (int j = 0; j < 8; j++) pv[j] = catw(B0, B1, br, n0 + bc + j);
    } else {
        float4 b0 = *(const float4*)(B0 + (size_t)br * CC + n0 + bc);
        float4 b1 = *(const float4*)(B0 + (size_t)br * CC + n0 + bc + 4);
        pv[0] = b0.x; pv[1] = b0.y; pv[2] = b0.z; pv[3] = b0.w;
        pv[4] = b1.x; pv[5] = b1.y; pv[6] = b1.z; pv[7] = b1.w;
    }
    {
        float av[8] = {pa0.x, pa0.y, pa0.z, pa0.w, pa1.x, pa1.y, pa1.z, pa1.w};
        if (ATRANS == 2) {
            #pragma unroll
            for (int j = 0; j < 8; j++)
                av[j] = gelu_exact((av[j] - mu[j]) * rs[j] * pgk + pbk);
        }
        if (ATRANS) {
            // tile index nl = bc + j -> perm = j*16 + bq
            #pragma unroll
            for (int j = 0; j < 8; j++) As[0][br][j * 16 + bq] = tf32r(av[j]);
        } else {
            // element (k = ac+j, m = ar) -> perm(ar) = (ar&7)*16 + (ar>>3)
            int pm = (ar & 7) * 16 + (ar >> 3);
            #pragma unroll
            for (int j = 0; j < 8; j++) As[0][ac + j][pm] = tf32r(av[j]);
        }
        #pragma unroll
        for (int j = 0; j < 8; j++) Bs[0][br][j * 16 + bq] = tf32r(pv[j]);
    }
    __syncthreads();

    int aoff = gid * 16 + wm * 4;   // A fragment perm offset
    int boff = gid * 16 + wn * 8;   // B fragment perm offset

    for (int kt = 0; kt < NKT; kt++) {
        int cur = kt & 1;
        if (kt + 1 < NKT) {
            const float* An = ATRANS ? (Aptr + (size_t)(kt + 1) * GBK * HWSZ)
                                     : (Aptr + (kt + 1) * GBK);
            pa0 = *(const float4*)(An + 0);
            pa1 = *(const float4*)(An + 4);
            int kn = (kt + 1) * GBK + br;
            if (ATRANS == 2) { pgk = lng[kn]; pbk = lnb[kn]; }
            if (BKIND == 2) {
                #pragma unroll
                for (int j = 0; j < 8; j++) pv[j] = catw(B0, B1, kn, n0 + bc + j);
            } else {
                float4 b0 = *(const float4*)(B0 + (size_t)kn * CC + n0 + bc);
                float4 b1 = *(const float4*)(B0 + (size_t)kn * CC + n0 + bc + 4);
                pv[0] = b0.x; pv[1] = b0.y; pv[2] = b0.z; pv[3] = b0.w;
                pv[4] = b1.x; pv[5] = b1.y; pv[6] = b1.z; pv[7] = b1.w;
            }
        }
        #pragma unroll
        for (int ks = 0; ks < 2; ks++) {
            int r0 = ks * 8 + tid4;
            int r1 = r0 + 4;
            // A fragments: m = wm*32 + {0,8,16,24} + gid  (covers both mt)
            float4 a0 = *(const float4*)&As[cur][r0][aoff];
            float4 a1 = *(const float4*)&As[cur][r1][aoff];
            // B fragments: n = wn*64 + nt*8 + gid, nt = 0..7
            float4 b0a = *(const float4*)&Bs[cur][r0][boff];
            float4 b0b = *(const float4*)&Bs[cur][r0][boff + 4];
            float4 b1a = *(const float4*)&Bs[cur][r1][boff];
            float4 b1b = *(const float4*)&Bs[cur][r1][boff + 4];

            uint32_t af[2][4];
            af[0][0] = __float_as_uint(a0.x); af[0][1] = __float_as_uint(a0.y);
            af[0][2] = __float_as_uint(a1.x); af[0][3] = __float_as_uint(a1.y);
            af[1][0] = __float_as_uint(a0.z); af[1][1] = __float_as_uint(a0.w);
            af[1][2] = __float_as_uint(a1.z); af[1][3] = __float_as_uint(a1.w);

            float b0arr[8] = {b0a.x, b0a.y, b0a.z, b0a.w, b0b.x, b0b.y, b0b.z, b0b.w};
            float b1arr[8] = {b1a.x, b1a.y, b1a.z, b1a.w, b1b.x, b1b.y, b1b.z, b1b.w};

            #pragma unroll
            for (int nt = 0; nt < 8; nt++) {
                uint32_t bf[2] = {__float_as_uint(b0arr[nt]), __float_as_uint(b1arr[nt])};
                mma_tf32(acc[0][nt], af[0], bf);
                mma_tf32(acc[1][nt], af[1], bf);
            }
        }
        if (kt + 1 < NKT) {
            int nxt = cur ^ 1;
            float av[8] = {pa0.x, pa0.y, pa0.z, pa0.w, pa1.x, pa1.y, pa1.z, pa1.w};
            if (ATRANS == 2) {
                #pragma unroll
                for (int j = 0; j < 8; j++)
                    av[j] = gelu_exact((av[j] - mu[j]) * rs[j] * pgk + pbk);
            }
            if (ATRANS) {
                #pragma unroll
                for (int j = 0; j < 8; j++) As[nxt][br][j * 16 + bq] = tf32r(av[j]);
            } else {
                int pm = (ar & 7) * 16 + (ar >> 3);
                #pragma unroll
                for (int j = 0; j < 8; j++) As[nxt][ac + j][pm] = tf32r(av[j]);
            }
            #pragma unroll
            for (int j = 0; j < 8; j++) Bs[nxt][br][j * 16 + bq] = tf32r(pv[j]);
            __syncthreads();
        }
    }

    #pragma unroll
    for (int mt = 0; mt < 2; mt++) {
        int r0 = m0 + wm * 32 + mt * 16 + gid;
        #pragma unroll
        for (int nt = 0; nt < 8; nt++) {
            int cb = n0 + wn * 64 + nt * 8 + 2 * tid4;
            float b0, b1;
            if (BKIND == 2) {
                b0 = (cb < NOFF) ? bias0[cb] : (cb < NOFF + NMSK) ? bias1[cb - NOFF] : 0.f;
                int c1i = cb + 1;
                b1 = (c1i < NOFF) ? bias0[c1i] : (c1i < NOFF + NMSK) ? bias1[c1i - NOFF] : 0.f;
            } else {
                b0 = bias0[cb]; b1 = bias0[cb + 1];
            }
            if (STORE_NCHW) {
                int n0b = r0 >> 12, hw0 = r0 & 4095;
                int n1b = (r0 + 8) >> 12, hw1 = (r0 + 8) & 4095;
                Cout[((size_t)n0b * CC + cb    ) * HWSZ + hw0] = acc[mt][nt][0] + b0;
                Cout[((size_t)n0b * CC + cb + 1) * HWSZ + hw0] = acc[mt][nt][1] + b1;
                Cout[((size_t)n1b * CC + cb    ) * HWSZ + hw1] = acc[mt][nt][2] + b0;
                Cout[((size_t)n1b * CC + cb + 1) * HWSZ + hw1] = acc[mt][nt][3] + b1;
            } else {
                Cout[(size_t)r0 * NCAT + cb]           = acc[mt][nt][0] + b0;
                Cout[(size_t)r0 * NCAT + cb + 1]       = acc[mt][nt][1] + b1;
                Cout[(size_t)(r0 + 8) * NCAT + cb]     = acc[mt][nt][2] + b0;
                Cout[(size_t)(r0 + 8) * NCAT + cb + 1] = acc[mt][nt][3] + b1;
            }
        }
    }
}

// ---------------------------------------------------------------------------
// 1) Fused launch: value-proj GEMM (blocks 0..255) + depthwise conv (rest)
// ---------------------------------------------------------------------------
__global__ void __launch_bounds__(256, 2)
conv_gemm_kernel(const float* __restrict__ in,
                 const float* __restrict__ w_in,
                 const float* __restrict__ b_in,
                 const float* __restrict__ dwk,
                 const float* __restrict__ dwb) {
    __shared__ float smem[SMEM_FLOATS];
    if (blockIdx.x < 256) {
        gemm_body<1, 0, 0>(in, w_in, w_in, b_in, b_in, b_in, b_in, g_xv,
                           blockIdx.x & 1, blockIdx.x >> 1, smem);
        return;
    }
    float (*sp)[66] = (float (*)[66])smem;
    int b = blockIdx.x - 256;
    int n = b >> 8, c = b & 255;
    int tid = threadIdx.x;

    for (int i = tid; i < 66 * 66; i += 256) ((float*)sp)[i] = 0.f;
    __syncthreads();

    const float* src = in + ((size_t)n * CC + c) * HWSZ;
    for (int i = tid; i < HWSZ; i += 256) {
        int h = i >> 6, w = i & 63;
        sp[h + 1][w + 1] = src[i];
    }
    __syncthreads();

    float k00 = dwk[0 * CC + c], k01 = dwk[1 * CC + c], k02 = dwk[2 * CC + c];
    float k10 = dwk[3 * CC + c], k11 = dwk[4 * CC + c], k12 = dwk[5 * CC + c];
    float k20 = dwk[6 * CC + c], k21 = dwk[7 * CC + c], k22 = dwk[8 * CC + c];
    float bb  = dwb[c];

    float* dst = g_c1 + ((size_t)n * CC + c) * HWSZ;
    for (int i = tid; i < HWSZ; i += 256) {
        int h = i >> 6, w = i & 63;
        float acc = bb;
        acc = fmaf(sp[h    ][w    ], k00, acc);
        acc = fmaf(sp[h    ][w + 1], k01, acc);
        acc = fmaf(sp[h    ][w + 2], k02, acc);
        acc = fmaf(sp[h + 1][w    ], k10, acc);
        acc = fmaf(sp[h + 1][w + 1], k11, acc);
        acc = fmaf(sp[h + 1][w + 2], k12, acc);
        acc = fmaf(sp[h + 2][w    ], k20, acc);
        acc = fmaf(sp[h + 2][w + 1], k21, acc);
        acc = fmaf(sp[h + 2][w + 2], k22, acc);
        dst[i] = acc;
    }
}

// om GEMM: A from g_c1 with fused LN+GELU; B = concat [w_off|w_mask|0]
__global__ void __launch_bounds__(256, 2)
gemm_om_kernel(const float* __restrict__ w_off, const float* __restrict__ w_mask,
               const float* __restrict__ b_off, const float* __restrict__ b_mask,
               const float* __restrict__ lng, const float* __restrict__ lnb,
               float* __restrict__ Cout) {
    __shared__ float smem[SMEM_FLOATS];
    gemm_body<2, 2, 0>(g_c1, w_off, w_mask, b_off, b_mask, lng, lnb, Cout,
                       blockIdx.x & 1, blockIdx.x >> 1, smem);
}

__global__ void __launch_bounds__(256, 2)
gemm_out_kernel(const float* __restrict__ A, const float* __restrict__ B,
                const float* __restrict__ bias, float* __restrict__ Cout) {
    __shared__ float smem[SMEM_FLOATS];
    gemm_body<0, 0, 1>(A, B, B, bias, bias, bias, bias, Cout,
                       blockIdx.x & 1, blockIdx.x >> 1, smem);
}

// ---------------------------------------------------------------------------
// 2) LN stats only: per-token mean + rsqrt(var+eps) from NCHW conv output.
// ---------------------------------------------------------------------------
__global__ void __launch_bounds__(256)
ln_stats_kernel() {
    __shared__ float tile[256][33];

    int tid = threadIdx.x;
    int t0 = blockIdx.x * 32;
    int n = t0 >> 12, hw0 = t0 & 4095;

    const float* src = g_c1 + (size_t)n * CC * HWSZ + hw0;
    int tx = tid & 31, ty = tid >> 5;
    #pragma unroll 4
    for (int cc = 0; cc < 32; cc++) {
        int ch = cc * 8 + ty;
        tile[ch][tx] = src[(size_t)ch * HWSZ + tx];
    }
    __syncthreads();

    int tok = tid >> 3, thr = tid & 7;
    float s1 = 0.f, s2 = 0.f;
    #pragma unroll 8
    for (int i = 0; i < 32; i++) {
        float v = tile[thr + 8 * i][tok];
        s1 += v; s2 += v * v;
    }
    #pragma unroll
    for (int d = 1; d < 8; d <<= 1) {
        s1 += __shfl_xor_sync(0xffffffffu, s1, d);
        s2 += __shfl_xor_sync(0xffffffffu, s2, d);
    }
    if (thr == 0) {
        float mu = s1 * (1.0f / 256.0f);
        float var = s2 * (1.0f / 256.0f) - mu * mu;
        g_mu[t0 + tok] = mu;
        g_rs[t0 + tok] = rsqrtf(var + 1e-6f);
    }
}

// ---------------------------------------------------------------------------
// 5+6) DCNv3 sampling + fused softmax — R4 one-phase form (measured 38.8us).
// ---------------------------------------------------------------------------
__global__ void __launch_bounds__(256)
dcn_kernel() {
    int tid = threadIdx.x;
    int t   = blockIdx.x * 4 + (tid >> 6);
    int sub = tid & 63;
    int g   = sub >> 3, l8 = sub & 7;
    int n = t >> 12, hw = t & 4095, h = hw >> 6, w = hw & 63;

    const float* off = g_om + (size_t)t * NCAT + g * (PP * 2);
    const float* lg  = g_om + (size_t)t * NCAT + NOFF + g * PP;
    const float4* xvb = (const float4*)(g_xv + (size_t)n * HWSZ * CC + g * CG) + l8;

    float e[PP];
    float mx = lg[0];
    #pragma unroll
    for (int p = 1; p < PP; p++) mx = fmaxf(mx, lg[p]);
    float s = 0.f;
    #pragma unroll
    for (int p = 0; p < PP; p++) { e[p] = __expf(lg[p] - mx); s += e[p]; }
    float inv = 1.0f / s;

    float ax = 0.f, ay = 0.f, az = 0.f, aw = 0.f;
    #pragma unroll
    for (int p = 0; p < PP; p++) {
        float kx = (float)(p / 3 - 1);
        float ky = (float)(p % 3 - 1);
        float px = (float)w + 1.0f + 2.0f * (kx + off[p * 2 + 0]);
        float py = (float)h + 1.0f + 2.0f * (ky + off[p * 2 + 1]);
        float x0f = floorf(px), y0f = floorf(py);
        float wx = px - x0f, wy = py - y0f;
        int x0 = (int)x0f, y0 = (int)y0f;
        float m = e[p] * inv;

        bool bx0 = (x0 >= 1) & (x0 <= WW);
        bool bx1 = (x0 >= 0) & (x0 <= WW - 1);
        bool by0 = (y0 >= 1) & (y0 <= HH);
        bool by1 = (y0 >= 0) & (y0 <= HH - 1);

        float4 v00 = {0,0,0,0}, v01 = {0,0,0,0}, v10 = {0,0,0,0}, v11 = {0,0,0,0};
        if (bx0 & by0) v00 = xvb[(size_t)((y0 - 1) * WW + (x0 - 1)) * (CC / 4)];
        if (bx1 & by0) v01 = xvb[(size_t)((y0 - 1) * WW + x0) * (CC / 4)];
        if (bx0 & by1) v10 = xvb[(size_t)(y0 * WW + (x0 - 1)) * (CC / 4)];
        if (bx1 & by1) v11 = xvb[(size_t)(y0 * WW + x0) * (CC / 4)];

        float w00 = m * (1.f - wx) * (1.f - wy);
        float w01 = m * wx * (1.f - wy);
        float w10 = m * (1.f - wx) * wy;
        float w11 = m * wx * wy;

        ax = fmaf(w00, v00.x, fmaf(w01, v01.x, fmaf(w10, v10.x, fmaf(w11, v11.x, ax))));
        ay = fmaf(w00, v00.y, fmaf(w01, v01.y, fmaf(w10, v10.y, fmaf(w11, v11.y, ay))));
        az = fmaf(w00, v00.z, fmaf(w01, v01.z, fmaf(w10, v10.z, fmaf(w11, v11.z, az))));
        aw = fmaf(w00, v00.w, fmaf(w01, v01.w, fmaf(w10, v10.w, fmaf(w11, v11.w, aw))));
    }
    ((float4*)(g_y + (size_t)t * CC + g * CG))[l8] = make_float4(ax, ay, az, aw);
}

// ---------------------------------------------------------------------------
extern "C" void kernel_launch(void* const* d_in, const int* in_sizes, int n_in,
                              void* d_out, int out_size) {
    const float* inputs = (const float*)d_in[0];
    const float* w_in   = (const float*)d_in[1];
    const float* b_in   = (const float*)d_in[2];
    const float* dw_k   = (const float*)d_in[3];
    const float* dw_b   = (const float*)d_in[4];
    const float* ln_g   = (const float*)d_in[5];
    const float* ln_b   = (const float*)d_in[6];
    const float* w_off  = (const float*)d_in[7];
    const float* b_off  = (const float*)d_in[8];
    const float* w_mask = (const float*)d_in[9];
    const float* b_mask = (const float*)d_in[10];
    const float* w_out  = (const float*)d_in[11];
    const float* b_out  = (const float*)d_in[12];
    float* out = (float*)d_out;

    static float *p_om = nullptr, *p_y = nullptr;
    if (!p_om) {
        cudaGetSymbolAddress((void**)&p_om, g_om);
        cudaGetSymbolAddress((void**)&p_y,  g_y);
    }

    // 1) fused: value-proj GEMM + depthwise conv
    conv_gemm_kernel<<<256 + NB * CC, 256>>>(inputs, w_in, b_in, dw_k, dw_b);
    // 2) LN stats (mean + rsig per token)
    ln_stats_kernel<<<MTOK / 32, 256>>>();
    // 3) offset + mask logits; LN+GELU fused into A staging
    gemm_om_kernel<<<256, 256>>>(w_off, w_mask, b_off, b_mask, ln_g, ln_b, p_om);
    // 4) softmax + deformable sampling (one-phase, R4 form)
    dcn_kernel<<<MTOK / 4, 256>>>();
    // 5) output projection, NCHW store
    gemm_out_kernel<<<256, 256>>>(p_y, w_out, b_out, out);
}

// round 15
// speedup vs baseline: 1.5822x; 1.5822x over previous
#include <cuda_runtime.h>
#include <math.h>
#include <stdint.h>

// Problem constants
#define NB   4
#define CC   256
#define HH   64
#define WW   64
#define HWSZ 4096        // H*W
#define MTOK 16384       // N*H*W tokens
#define GG   8
#define PP   9
#define CG   32          // C/G
#define NOFF 144         // G*P*2
#define NMSK 72          // G*P
#define NCAT 256         // padded off|mask column count

// Scratch (no allocs allowed)
__device__ float g_c1 [MTOK * CC];    // depthwise conv output, NCHW
__device__ float g_xv [MTOK * CC];    // value proj, NHWC
__device__ float g_om [MTOK * NCAT];  // offset(0..143) | mask logits(144..215) | pad
__device__ float g_y  [MTOK * CC];    // sampled output, NHWC
__device__ float g_mu [MTOK];         // LN mean per token
__device__ float g_rs [MTOK];         // LN rsqrt(var+eps) per token

__device__ __forceinline__ float tf32r(float x) {
    uint32_t u;
    asm("cvt.rna.tf32.f32 %0, %1;" : "=r"(u) : "f"(x));
    return __uint_as_float(u);
}

__device__ __forceinline__ float gelu_exact(float v) {
    return 0.5f * v * (1.0f + erff(v * 0.70710678118654752f));
}

__device__ __forceinline__ void mma_tf32(float d[4], const uint32_t a[4], const uint32_t b[2]) {
    asm("mma.sync.aligned.m16n8k8.row.col.f32.tf32.tf32.f32 "
        "{%0,%1,%2,%3}, {%4,%5,%6,%7}, {%8,%9}, {%0,%1,%2,%3};"
        : "+f"(d[0]), "+f"(d[1]), "+f"(d[2]), "+f"(d[3])
        : "r"(a[0]), "r"(a[1]), "r"(a[2]), "r"(a[3]), "r"(b[0]), "r"(b[1]));
}

// concat weight gather: [w_off | w_mask | 0]
__device__ __forceinline__ float catw(const float* __restrict__ w_off,
                                      const float* __restrict__ w_mask,
                                      int k, int col) {
    if (col < NOFF) return w_off[k * NOFF + col];
    if (col < NOFF + NMSK) return w_mask[k * NMSK + (col - NOFF)];
    return 0.f;
}

// ---------------------------------------------------------------------------
// TF32 GEMM body: C[M,256] = A[M,256] @ B[256,256] + bias
// ATRANS=0: A row-major [M,K]. ATRANS=1: A from NCHW (per-n column-major).
// ATRANS=2: like 1 but from g_c1 with fused LayerNorm+GELU applied at staging.
// BKIND=0: plain B. BKIND=2: concat [w_off|w_mask|0].
// STORE_NCHW=1: store to NCHW [4][256][4096].
// ---------------------------------------------------------------------------
#define GBM 128
#define GBN 128
#define GBK 16
#define SPAD 136
#define KTOT 256
#define NKT (KTOT / GBK)
#define SMEM_FLOATS (2 * GBK * SPAD * 2)   // 8704 floats = 34816 B

template<int ATRANS, int BKIND, int STORE_NCHW>
__device__ __forceinline__ void gemm_body(
    const float* __restrict__ A,
    const float* __restrict__ B0, const float* __restrict__ B1,
    const float* __restrict__ bias0, const float* __restrict__ bias1,
    const float* __restrict__ lng, const float* __restrict__ lnb,
    float* __restrict__ Cout, int bx, int by, float* smem)
{
    float (*As)[GBK][SPAD] = (float (*)[GBK][SPAD])smem;
    float (*Bs)[GBK][SPAD] = (float (*)[GBK][SPAD])(smem + 2 * GBK * SPAD);

    int tid  = threadIdx.x;
    int lane = tid & 31;
    int warp = tid >> 5;
    int gid  = lane >> 2;
    int tid4 = lane & 3;
    int wm   = warp >> 1;
    int wn   = warp & 1;
    int m0   = by * GBM;
    int n0   = bx * GBN;

    int ar = tid >> 1;
    int ac = (tid & 1) * 8;
    int br = tid >> 4;
    int bc = (tid & 15) * 8;

    const float* Aptr;
    if (ATRANS) {
        Aptr = A + (size_t)(m0 >> 12) * CC * HWSZ + (size_t)br * HWSZ + (m0 & 4095) + bc;
    } else {
        Aptr = A + (size_t)(m0 + ar) * KTOT + ac;
    }

    // LN per-column stats (token = m0+bc..+7), invariant over k
    float mu[8], rs[8];
    if (ATRANS == 2) {
        float4 m04 = *(const float4*)(g_mu + m0 + bc);
        float4 m14 = *(const float4*)(g_mu + m0 + bc + 4);
        float4 r04 = *(const float4*)(g_rs + m0 + bc);
        float4 r14 = *(const float4*)(g_rs + m0 + bc + 4);
        mu[0] = m04.x; mu[1] = m04.y; mu[2] = m04.z; mu[3] = m04.w;
        mu[4] = m14.x; mu[5] = m14.y; mu[6] = m14.z; mu[7] = m14.w;
        rs[0] = r04.x; rs[1] = r04.y; rs[2] = r04.z; rs[3] = r04.w;
        rs[4] = r14.x; rs[5] = r14.y; rs[6] = r14.z; rs[7] = r14.w;
    }

    float acc[2][8][4];
    #pragma unroll
    for (int i = 0; i < 2; i++)
        #pragma unroll
        for (int j = 0; j < 8; j++)
            #pragma unroll
            for (int q = 0; q < 4; q++) acc[i][j][q] = 0.f;

    float4 pa0, pa1;
    float pv[8];
    float pgk = 0.f, pbk = 0.f;

    // prologue: k-tile 0
    pa0 = *(const float4*)(Aptr + 0);
    pa1 = *(const float4*)(Aptr + 4);
    if (ATRANS == 2) { pgk = lng[br]; pbk = lnb[br]; }
    if (BKIND == 2) {
        #pragma unroll
        for (int j = 0; j < 8; j++) pv[j] = catw(B0, B1, br, n0 + bc + j);
    } else {
        float4 b0 = *(const float4*)(B0 + (size_t)br * CC + n0 + bc);
        float4 b1 = *(const float4*)(B0 + (size_t)br * CC + n0 + bc + 4);
        pv[0] = b0.x; pv[1] = b0.y; pv[2] = b0.z; pv[3] = b0.w;
        pv[4] = b1.x; pv[5] = b1.y; pv[6] = b1.z; pv[7] = b1.w;
    }
    {
        float av[8] = {pa0.x, pa0.y, pa0.z, pa0.w, pa1.x, pa1.y, pa1.z, pa1.w};
        if (ATRANS == 2) {
            #pragma unroll
            for (int j = 0; j < 8; j++)
                av[j] = gelu_exact((av[j] - mu[j]) * rs[j] * pgk + pbk);
        }
        if (ATRANS) {
            #pragma unroll
            for (int j = 0; j < 8; j++) As[0][br][bc + j] = tf32r(av[j]);
        } else {
            #pragma unroll
            for (int j = 0; j < 8; j++) As[0][ac + j][ar] = tf32r(av[j]);
        }
        #pragma unroll
        for (int j = 0; j < 8; j++) Bs[0][br][bc + j] = tf32r(pv[j]);
    }
    __syncthreads();

    for (int kt = 0; kt < NKT; kt++) {
        int cur = kt & 1;
        if (kt + 1 < NKT) {
            const float* An = ATRANS ? (Aptr + (size_t)(kt + 1) * GBK * HWSZ)
                                     : (Aptr + (kt + 1) * GBK);
            pa0 = *(const float4*)(An + 0);
            pa1 = *(const float4*)(An + 4);
            int kn = (kt + 1) * GBK + br;
            if (ATRANS == 2) { pgk = lng[kn]; pbk = lnb[kn]; }
            if (BKIND == 2) {
                #pragma unroll
                for (int j = 0; j < 8; j++) pv[j] = catw(B0, B1, kn, n0 + bc + j);
            } else {
                float4 b0 = *(const float4*)(B0 + (size_t)kn * CC + n0 + bc);
                float4 b1 = *(const float4*)(B0 + (size_t)kn * CC + n0 + bc + 4);
                pv[0] = b0.x; pv[1] = b0.y; pv[2] = b0.z; pv[3] = b0.w;
                pv[4] = b1.x; pv[5] = b1.y; pv[6] = b1.z; pv[7] = b1.w;
            }
        }
        #pragma unroll
        for (int ks = 0; ks < 2; ks++) {
            int kk = ks * 8;
            uint32_t af[2][4], bf[8][2];
            #pragma unroll
            for (int mt = 0; mt < 2; mt++) {
                int mb = wm * 32 + mt * 16;
                af[mt][0] = __float_as_uint(As[cur][kk + tid4    ][mb + gid    ]);
                af[mt][1] = __float_as_uint(As[cur][kk + tid4    ][mb + gid + 8]);
                af[mt][2] = __float_as_uint(As[cur][kk + tid4 + 4][mb + gid    ]);
                af[mt][3] = __float_as_uint(As[cur][kk + tid4 + 4][mb + gid + 8]);
            }
            #pragma unroll
            for (int nt = 0; nt < 8; nt++) {
                int nb = wn * 64 + nt * 8;
                bf[nt][0] = __float_as_uint(Bs[cur][kk + tid4    ][nb + gid]);
                bf[nt][1] = __float_as_uint(Bs[cur][kk + tid4 + 4][nb + gid]);
            }
            #pragma unroll
            for (int mt = 0; mt < 2; mt++)
                #pragma unroll
                for (int nt = 0; nt < 8; nt++)
                    mma_tf32(acc[mt][nt], af[mt], bf[nt]);
        }
        if (kt + 1 < NKT) {
            int nxt = cur ^ 1;
            float av[8] = {pa0.x, pa0.y, pa0.z, pa0.w, pa1.x, pa1.y, pa1.z, pa1.w};
            if (ATRANS == 2) {
                #pragma unroll
                for (int j = 0; j < 8; j++)
                    av[j] = gelu_exact((av[j] - mu[j]) * rs[j] * pgk + pbk);
            }
            if (ATRANS) {
                #pragma unroll
                for (int j = 0; j < 8; j++) As[nxt][br][bc + j] = tf32r(av[j]);
            } else {
                #pragma unroll
                for (int j = 0; j < 8; j++) As[nxt][ac + j][ar] = tf32r(av[j]);
            }
            #pragma unroll
            for (int j = 0; j < 8; j++) Bs[nxt][br][bc + j] = tf32r(pv[j]);
            __syncthreads();
        }
    }

    #pragma unroll
    for (int mt = 0; mt < 2; mt++) {
        int r0 = m0 + wm * 32 + mt * 16 + gid;
        #pragma unroll
        for (int nt = 0; nt < 8; nt++) {
            int cb = n0 + wn * 64 + nt * 8 + 2 * tid4;
            float b0, b1;
            if (BKIND == 2) {
                b0 = (cb < NOFF) ? bias0[cb] : (cb < NOFF + NMSK) ? bias1[cb - NOFF] : 0.f;
                int c1i = cb + 1;
                b1 = (c1i < NOFF) ? bias0[c1i] : (c1i < NOFF + NMSK) ? bias1[c1i - NOFF] : 0.f;
            } else {
                b0 = bias0[cb]; b1 = bias0[cb + 1];
            }
            if (STORE_NCHW) {
                int n0b = r0 >> 12, hw0 = r0 & 4095;
                int n1b = (r0 + 8) >> 12, hw1 = (r0 + 8) & 4095;
                Cout[((size_t)n0b * CC + cb    ) * HWSZ + hw0] = acc[mt][nt][0] + b0;
                Cout[((size_t)n0b * CC + cb + 1) * HWSZ + hw0] = acc[mt][nt][1] + b1;
                Cout[((size_t)n1b * CC + cb    ) * HWSZ + hw1] = acc[mt][nt][2] + b0;
                Cout[((size_t)n1b * CC + cb + 1) * HWSZ + hw1] = acc[mt][nt][3] + b1;
            } else {
                Cout[(size_t)r0 * NCAT + cb]           = acc[mt][nt][0] + b0;
                Cout[(size_t)r0 * NCAT + cb + 1]       = acc[mt][nt][1] + b1;
                Cout[(size_t)(r0 + 8) * NCAT + cb]     = acc[mt][nt][2] + b0;
                Cout[(size_t)(r0 + 8) * NCAT + cb + 1] = acc[mt][nt][3] + b1;
            }
        }
    }
}

// ---------------------------------------------------------------------------
// 1) Fused launch: value-proj GEMM (blocks 0..255) + depthwise conv (rest)
// ---------------------------------------------------------------------------
__global__ void __launch_bounds__(256, 2)
conv_gemm_kernel(const float* __restrict__ in,
                 const float* __restrict__ w_in,
                 const float* __restrict__ b_in,
                 const float* __restrict__ dwk,
                 const float* __restrict__ dwb) {
    __shared__ float smem[SMEM_FLOATS];
    if (blockIdx.x < 256) {
        gemm_body<1, 0, 0>(in, w_in, w_in, b_in, b_in, b_in, b_in, g_xv,
                           blockIdx.x & 1, blockIdx.x >> 1, smem);
        return;
    }
    float (*sp)[66] = (float (*)[66])smem;
    int b = blockIdx.x - 256;
    int n = b >> 8, c = b & 255;
    int tid = threadIdx.x;

    for (int i = tid; i < 66 * 66; i += 256) ((float*)sp)[i] = 0.f;
    __syncthreads();

    const float* src = in + ((size_t)n * CC + c) * HWSZ;
    for (int i = tid; i < HWSZ; i += 256) {
        int h = i >> 6, w = i & 63;
        sp[h + 1][w + 1] = src[i];
    }
    __syncthreads();

    float k00 = dwk[0 * CC + c], k01 = dwk[1 * CC + c], k02 = dwk[2 * CC + c];
    float k10 = dwk[3 * CC + c], k11 = dwk[4 * CC + c], k12 = dwk[5 * CC + c];
    float k20 = dwk[6 * CC + c], k21 = dwk[7 * CC + c], k22 = dwk[8 * CC + c];
    float bb  = dwb[c];

    float* dst = g_c1 + ((size_t)n * CC + c) * HWSZ;
    for (int i = tid; i < HWSZ; i += 256) {
        int h = i >> 6, w = i & 63;
        float acc = bb;
        acc = fmaf(sp[h    ][w    ], k00, acc);
        acc = fmaf(sp[h    ][w + 1], k01, acc);
        acc = fmaf(sp[h    ][w + 2], k02, acc);
        acc = fmaf(sp[h + 1][w    ], k10, acc);
        acc = fmaf(sp[h + 1][w + 1], k11, acc);
        acc = fmaf(sp[h + 1][w + 2], k12, acc);
        acc = fmaf(sp[h + 2][w    ], k20, acc);
        acc = fmaf(sp[h + 2][w + 1], k21, acc);
        acc = fmaf(sp[h + 2][w + 2], k22, acc);
        dst[i] = acc;
    }
}

// om GEMM: A from g_c1 with fused LN+GELU; B = concat [w_off|w_mask|0]
__global__ void __launch_bounds__(256, 2)
gemm_om_kernel(const float* __restrict__ w_off, const float* __restrict__ w_mask,
               const float* __restrict__ b_off, const float* __restrict__ b_mask,
               const float* __restrict__ lng, const float* __restrict__ lnb,
               float* __restrict__ Cout) {
    __shared__ float smem[SMEM_FLOATS];
    gemm_body<2, 2, 0>(g_c1, w_off, w_mask, b_off, b_mask, lng, lnb, Cout,
                       blockIdx.x & 1, blockIdx.x >> 1, smem);
}

__global__ void __launch_bounds__(256, 2)
gemm_out_kernel(const float* __restrict__ A, const float* __restrict__ B,
                const float* __restrict__ bias, float* __restrict__ Cout) {
    __shared__ float smem[SMEM_FLOATS];
    gemm_body<0, 0, 1>(A, B, B, bias, bias, bias, bias, Cout,
                       blockIdx.x & 1, blockIdx.x >> 1, smem);
}

// ---------------------------------------------------------------------------
// 2) LN stats only: per-token mean + rsqrt(var+eps) from NCHW conv output.
// ---------------------------------------------------------------------------
__global__ void __launch_bounds__(256)
ln_stats_kernel() {
    __shared__ float tile[256][33];

    int tid = threadIdx.x;
    int t0 = blockIdx.x * 32;
    int n = t0 >> 12, hw0 = t0 & 4095;

    const float* src = g_c1 + (size_t)n * CC * HWSZ + hw0;
    int tx = tid & 31, ty = tid >> 5;
    #pragma unroll 4
    for (int cc = 0; cc < 32; cc++) {
        int ch = cc * 8 + ty;
        tile[ch][tx] = src[(size_t)ch * HWSZ + tx];
    }
    __syncthreads();

    int tok = tid >> 3, thr = tid & 7;
    float s1 = 0.f, s2 = 0.f;
    #pragma unroll 8
    for (int i = 0; i < 32; i++) {
        float v = tile[thr + 8 * i][tok];
        s1 += v; s2 += v * v;
    }
    #pragma unroll
    for (int d = 1; d < 8; d <<= 1) {
        s1 += __shfl_xor_sync(0xffffffffu, s1, d);
        s2 += __shfl_xor_sync(0xffffffffu, s2, d);
    }
    if (thr == 0) {
        float mu = s1 * (1.0f / 256.0f);
        float var = s2 * (1.0f / 256.0f) - mu * mu;
        g_mu[t0 + tok] = mu;
        g_rs[t0 + tok] = rsqrtf(var + 1e-6f);
    }
}

// ---------------------------------------------------------------------------
// 5+6) DCNv3 sampling + fused softmax — R4 one-phase form (measured 38.8us).
// ---------------------------------------------------------------------------
__global__ void __launch_bounds__(256)
dcn_kernel() {
    int tid = threadIdx.x;
    int t   = blockIdx.x * 4 + (tid >> 6);
    int sub = tid & 63;
    int g   = sub >> 3, l8 = sub & 7;
    int n = t >> 12, hw = t & 4095, h = hw >> 6, w = hw & 63;

    const float* off = g_om + (size_t)t * NCAT + g * (PP * 2);
    const float* lg  = g_om + (size_t)t * NCAT + NOFF + g * PP;
    const float4* xvb = (const float4*)(g_xv + (size_t)n * HWSZ * CC + g * CG) + l8;

    float e[PP];
    float mx = lg[0];
    #pragma unroll
    for (int p = 1; p < PP; p++) mx = fmaxf(mx, lg[p]);
    float s = 0.f;
    #pragma unroll
    for (int p = 0; p < PP; p++) { e[p] = __expf(lg[p] - mx); s += e[p]; }
    float inv = 1.0f / s;

    float ax = 0.f, ay = 0.f, az = 0.f, aw = 0.f;
    #pragma unroll
    for (int p = 0; p < PP; p++) {
        float kx = (float)(p / 3 - 1);
        float ky = (float)(p % 3 - 1);
        float px = (float)w + 1.0f + 2.0f * (kx + off[p * 2 + 0]);
        float py = (float)h + 1.0f + 2.0f * (ky + off[p * 2 + 1]);
        float x0f = floorf(px), y0f = floorf(py);
        float wx = px - x0f, wy = py - y0f;
        int x0 = (int)x0f, y0 = (int)y0f;
        float m = e[p] * inv;

        bool bx0 = (x0 >= 1) & (x0 <= WW);
        bool bx1 = (x0 >= 0) & (x0 <= WW - 1);
        bool by0 = (y0 >= 1) & (y0 <= HH);
        bool by1 = (y0 >= 0) & (y0 <= HH - 1);

        float4 v00 = {0,0,0,0}, v01 = {0,0,0,0}, v10 = {0,0,0,0}, v11 = {0,0,0,0};
        if (bx0 & by0) v00 = xvb[(size_t)((y0 - 1) * WW + (x0 - 1)) * (CC / 4)];
        if (bx1 & by0) v01 = xvb[(size_t)((y0 - 1) * WW + x0) * (CC / 4)];
        if (bx0 & by1) v10 = xvb[(size_t)(y0 * WW + (x0 - 1)) * (CC / 4)];
        if (bx1 & by1) v11 = xvb[(size_t)(y0 * WW + x0) * (CC / 4)];

        float w00 = m * (1.f - wx) * (1.f - wy);
        float w01 = m * wx * (1.f - wy);
        float w10 = m * (1.f - wx) * wy;
        float w11 = m * wx * wy;

        ax = fmaf(w00, v00.x, fmaf(w01, v01.x, fmaf(w10, v10.x, fmaf(w11, v11.x, ax))));
        ay = fmaf(w00, v00.y, fmaf(w01, v01.y, fmaf(w10, v10.y, fmaf(w11, v11.y, ay))));
        az = fmaf(w00, v00.z, fmaf(w01, v01.z, fmaf(w10, v10.z, fmaf(w11, v11.z, az))));
        aw = fmaf(w00, v00.w, fmaf(w01, v01.w, fmaf(w10, v10.w, fmaf(w11, v11.w, aw))));
    }
    ((float4*)(g_y + (size_t)t * CC + g * CG))[l8] = make_float4(ax, ay, az, aw);
}

// ---------------------------------------------------------------------------
extern "C" void kernel_launch(void* const* d_in, const int* in_sizes, int n_in,
                              void* d_out, int out_size) {
    const float* inputs = (const float*)d_in[0];
    const float* w_in   = (const float*)d_in[1];
    const float* b_in   = (const float*)d_in[2];
    const float* dw_k   = (const float*)d_in[3];
    const float* dw_b   = (const float*)d_in[4];
    const float* ln_g   = (const float*)d_in[5];
    const float* ln_b   = (const float*)d_in[6];
    const float* w_off  = (const float*)d_in[7];
    const float* b_off  = (const float*)d_in[8];
    const float* w_mask = (const float*)d_in[9];
    const float* b_mask = (const float*)d_in[10];
    const float* w_out  = (const float*)d_in[11];
    const float* b_out  = (const float*)d_in[12];
    float* out = (float*)d_out;

    static float *p_om = nullptr, *p_y = nullptr;
    if (!p_om) {
        cudaGetSymbolAddress((void**)&p_om, g_om);
        cudaGetSymbolAddress((void**)&p_y,  g_y);
    }

    // 1) fused: value-proj GEMM + depthwise conv
    conv_gemm_kernel<<<256 + NB * CC, 256>>>(inputs, w_in, b_in, dw_k, dw_b);
    // 2) LN stats (mean + rsig per token)
    ln_stats_kernel<<<MTOK / 32, 256>>>();
    // 3) offset + mask logits; LN+GELU fused into A staging
    gemm_om_kernel<<<256, 256>>>(w_off, w_mask, b_off, b_mask, ln_g, ln_b, p_om);
    // 4) softmax + deformable sampling (one-phase, R4 form)
    dcn_kernel<<<MTOK / 4, 256>>>();
    // 5) output projection, NCHW store
    gemm_out_kernel<<<256, 256>>>(p_y, w_out, b_out, out);
}

// round 16
// speedup vs baseline: 1.5987x; 1.0104x over previous
#include <cuda_runtime.h>
#include <math.h>
#include <stdint.h>

// Problem constants
#define NB   4
#define CC   256
#define HH   64
#define WW   64
#define HWSZ 4096        // H*W
#define MTOK 16384       // N*H*W tokens
#define GG   8
#define PP   9
#define CG   32          // C/G
#define NOFF 144         // G*P*2
#define NMSK 72          // G*P
#define NCAT 256         // padded off|mask column count

// Scratch (no allocs allowed)
__device__ float g_c1 [MTOK * CC];    // depthwise conv output, NCHW
__device__ float g_xv [MTOK * CC];    // value proj, NHWC
__device__ float g_om [MTOK * NCAT];  // offset(0..143) | mask logits(144..215) | pad
__device__ float g_y  [MTOK * CC];    // sampled output, NHWC
__device__ float g_mu [MTOK];         // LN mean per token
__device__ float g_rs [MTOK];         // LN rsqrt(var+eps) per token

__device__ __forceinline__ float tf32r(float x) {
    uint32_t u;
    asm("cvt.rna.tf32.f32 %0, %1;" : "=r"(u) : "f"(x));
    return __uint_as_float(u);
}

__device__ __forceinline__ float gelu_exact(float v) {
    return 0.5f * v * (1.0f + erff(v * 0.70710678118654752f));
}

__device__ __forceinline__ void mma_tf32(float d[4], const uint32_t a[4], const uint32_t b[2]) {
    asm("mma.sync.aligned.m16n8k8.row.col.f32.tf32.tf32.f32 "
        "{%0,%1,%2,%3}, {%4,%5,%6,%7}, {%8,%9}, {%0,%1,%2,%3};"
        : "+f"(d[0]), "+f"(d[1]), "+f"(d[2]), "+f"(d[3])
        : "r"(a[0]), "r"(a[1]), "r"(a[2]), "r"(a[3]), "r"(b[0]), "r"(b[1]));
}

// concat weight gather: [w_off | w_mask | 0]
__device__ __forceinline__ float catw(const float* __restrict__ w_off,
                                      const float* __restrict__ w_mask,
                                      int k, int col) {
    if (col < NOFF) return w_off[k * NOFF + col];
    if (col < NOFF + NMSK) return w_mask[k * NMSK + (col - NOFF)];
    return 0.f;
}

// ---------------------------------------------------------------------------
// TF32 GEMM body (proven R11 form): C[M,256] = A[M,256] @ B[256,256] + bias
// ATRANS=0: A row-major [M,K]. ATRANS=1: A from NCHW (per-n column-major).
// ATRANS=2: like 1 but from g_c1 with fused LayerNorm+GELU applied at staging.
// BKIND=0: plain B. BKIND=2: concat [w_off|w_mask|0].
// STORE_NCHW=1: store to NCHW [4][256][4096].
// ---------------------------------------------------------------------------
#define GBM 128
#define GBN 128
#define GBK 16
#define SPAD 136
#define KTOT 256
#define NKT (KTOT / GBK)
#define SMEM_FLOATS (2 * GBK * SPAD * 2)   // 8704 floats = 34816 B

template<int ATRANS, int BKIND, int STORE_NCHW>
__device__ __forceinline__ void gemm_body(
    const float* __restrict__ A,
    const float* __restrict__ B0, const float* __restrict__ B1,
    const float* __restrict__ bias0, const float* __restrict__ bias1,
    const float* __restrict__ lng, const float* __restrict__ lnb,
    float* __restrict__ Cout, int bx, int by, float* smem)
{
    float (*As)[GBK][SPAD] = (float (*)[GBK][SPAD])smem;
    float (*Bs)[GBK][SPAD] = (float (*)[GBK][SPAD])(smem + 2 * GBK * SPAD);

    int tid  = threadIdx.x;
    int lane = tid & 31;
    int warp = tid >> 5;
    int gid  = lane >> 2;
    int tid4 = lane & 3;
    int wm   = warp >> 1;
    int wn   = warp & 1;
    int m0   = by * GBM;
    int n0   = bx * GBN;

    int ar = tid >> 1;
    int ac = (tid & 1) * 8;
    int br = tid >> 4;
    int bc = (tid & 15) * 8;

    const float* Aptr;
    if (ATRANS) {
        Aptr = A + (size_t)(m0 >> 12) * CC * HWSZ + (size_t)br * HWSZ + (m0 & 4095) + bc;
    } else {
        Aptr = A + (size_t)(m0 + ar) * KTOT + ac;
    }

    // LN per-column stats (token = m0+bc..+7), invariant over k
    float mu[8], rs[8];
    if (ATRANS == 2) {
        float4 m04 = *(const float4*)(g_mu + m0 + bc);
        float4 m14 = *(const float4*)(g_mu + m0 + bc + 4);
        float4 r04 = *(const float4*)(g_rs + m0 + bc);
        float4 r14 = *(const float4*)(g_rs + m0 + bc + 4);
        mu[0] = m04.x; mu[1] = m04.y; mu[2] = m04.z; mu[3] = m04.w;
        mu[4] = m14.x; mu[5] = m14.y; mu[6] = m14.z; mu[7] = m14.w;
        rs[0] = r04.x; rs[1] = r04.y; rs[2] = r04.z; rs[3] = r04.w;
        rs[4] = r14.x; rs[5] = r14.y; rs[6] = r14.z; rs[7] = r14.w;
    }

    float acc[2][8][4];
    #pragma unroll
    for (int i = 0; i < 2; i++)
        #pragma unroll
        for (int j = 0; j < 8; j++)
            #pragma unroll
            for (int q = 0; q < 4; q++) acc[i][j][q] = 0.f;

    float4 pa0, pa1;
    float pv[8];
    float pgk = 0.f, pbk = 0.f;

    // prologue: k-tile 0
    pa0 = *(const float4*)(Aptr + 0);
    pa1 = *(const float4*)(Aptr + 4);
    if (ATRANS == 2) { pgk = lng[br]; pbk = lnb[br]; }
    if (BKIND == 2) {
        #pragma unroll
        for (int j = 0; j < 8; j++) pv[j] = catw(B0, B1, br, n0 + bc + j);
    } else {
        float4 b0 = *(const float4*)(B0 + (size_t)br * CC + n0 + bc);
        float4 b1 = *(const float4*)(B0 + (size_t)br * CC + n0 + bc + 4);
        pv[0] = b0.x; pv[1] = b0.y; pv[2] = b0.z; pv[3] = b0.w;
        pv[4] = b1.x; pv[5] = b1.y; pv[6] = b1.z; pv[7] = b1.w;
    }
    {
        float av[8] = {pa0.x, pa0.y, pa0.z, pa0.w, pa1.x, pa1.y, pa1.z, pa1.w};
        if (ATRANS == 2) {
            #pragma unroll
            for (int j = 0; j < 8; j++)
                av[j] = gelu_exact((av[j] - mu[j]) * rs[j] * pgk + pbk);
        }
        if (ATRANS) {
            #pragma unroll
            for (int j = 0; j < 8; j++) As[0][br][bc + j] = tf32r(av[j]);
        } else {
            #pragma unroll
            for (int j = 0; j < 8; j++) As[0][ac + j][ar] = tf32r(av[j]);
        }
        #pragma unroll
        for (int j = 0; j < 8; j++) Bs[0][br][bc + j] = tf32r(pv[j]);
    }
    __syncthreads();

    for (int kt = 0; kt < NKT; kt++) {
        int cur = kt & 1;
        if (kt + 1 < NKT) {
            const float* An = ATRANS ? (Aptr + (size_t)(kt + 1) * GBK * HWSZ)
                                     : (Aptr + (kt + 1) * GBK);
            pa0 = *(const float4*)(An + 0);
            pa1 = *(const float4*)(An + 4);
            int kn = (kt + 1) * GBK + br;
            if (ATRANS == 2) { pgk = lng[kn]; pbk = lnb[kn]; }
            if (BKIND == 2) {
                #pragma unroll
                for (int j = 0; j < 8; j++) pv[j] = catw(B0, B1, kn, n0 + bc + j);
            } else {
                float4 b0 = *(const float4*)(B0 + (size_t)kn * CC + n0 + bc);
                float4 b1 = *(const float4*)(B0 + (size_t)kn * CC + n0 + bc + 4);
                pv[0] = b0.x; pv[1] = b0.y; pv[2] = b0.z; pv[3] = b0.w;
                pv[4] = b1.x; pv[5] = b1.y; pv[6] = b1.z; pv[7] = b1.w;
            }
        }
        #pragma unroll
        for (int ks = 0; ks < 2; ks++) {
            int kk = ks * 8;
            uint32_t af[2][4], bf[8][2];
            #pragma unroll
            for (int mt = 0; mt < 2; mt++) {
                int mb = wm * 32 + mt * 16;
                af[mt][0] = __float_as_uint(As[cur][kk + tid4    ][mb + gid    ]);
                af[mt][1] = __float_as_uint(As[cur][kk + tid4    ][mb + gid + 8]);
                af[mt][2] = __float_as_uint(As[cur][kk + tid4 + 4][mb + gid    ]);
                af[mt][3] = __float_as_uint(As[cur][kk + tid4 + 4][mb + gid + 8]);
            }
            #pragma unroll
            for (int nt = 0; nt < 8; nt++) {
                int nb = wn * 64 + nt * 8;
                bf[nt][0] = __float_as_uint(Bs[cur][kk + tid4    ][nb + gid]);
                bf[nt][1] = __float_as_uint(Bs[cur][kk + tid4 + 4][nb + gid]);
            }
            #pragma unroll
            for (int mt = 0; mt < 2; mt++)
                #pragma unroll
                for (int nt = 0; nt < 8; nt++)
                    mma_tf32(acc[mt][nt], af[mt], bf[nt]);
        }
        if (kt + 1 < NKT) {
            int nxt = cur ^ 1;
            float av[8] = {pa0.x, pa0.y, pa0.z, pa0.w, pa1.x, pa1.y, pa1.z, pa1.w};
            if (ATRANS == 2) {
                #pragma unroll
                for (int j = 0; j < 8; j++)
                    av[j] = gelu_exact((av[j] - mu[j]) * rs[j] * pgk + pbk);
            }
            if (ATRANS) {
                #pragma unroll
                for (int j = 0; j < 8; j++) As[nxt][br][bc + j] = tf32r(av[j]);
            } else {
                #pragma unroll
                for (int j = 0; j < 8; j++) As[nxt][ac + j][ar] = tf32r(av[j]);
            }
            #pragma unroll
            for (int j = 0; j < 8; j++) Bs[nxt][br][bc + j] = tf32r(pv[j]);
            __syncthreads();
        }
    }

    #pragma unroll
    for (int mt = 0; mt < 2; mt++) {
        int r0 = m0 + wm * 32 + mt * 16 + gid;
        #pragma unroll
        for (int nt = 0; nt < 8; nt++) {
            int cb = n0 + wn * 64 + nt * 8 + 2 * tid4;
            float b0, b1;
            if (BKIND == 2) {
                b0 = (cb < NOFF) ? bias0[cb] : (cb < NOFF + NMSK) ? bias1[cb - NOFF] : 0.f;
                int c1i = cb + 1;
                b1 = (c1i < NOFF) ? bias0[c1i] : (c1i < NOFF + NMSK) ? bias1[c1i - NOFF] : 0.f;
            } else {
                b0 = bias0[cb]; b1 = bias0[cb + 1];
            }
            if (STORE_NCHW) {
                int n0b = r0 >> 12, hw0 = r0 & 4095;
                int n1b = (r0 + 8) >> 12, hw1 = (r0 + 8) & 4095;
                Cout[((size_t)n0b * CC + cb    ) * HWSZ + hw0] = acc[mt][nt][0] + b0;
                Cout[((size_t)n0b * CC + cb + 1) * HWSZ + hw0] = acc[mt][nt][1] + b1;
                Cout[((size_t)n1b * CC + cb    ) * HWSZ + hw1] = acc[mt][nt][2] + b0;
                Cout[((size_t)n1b * CC + cb + 1) * HWSZ + hw1] = acc[mt][nt][3] + b1;
            } else {
                Cout[(size_t)r0 * NCAT + cb]           = acc[mt][nt][0] + b0;
                Cout[(size_t)r0 * NCAT + cb + 1]       = acc[mt][nt][1] + b1;
                Cout[(size_t)(r0 + 8) * NCAT + cb]     = acc[mt][nt][2] + b0;
                Cout[(size_t)(r0 + 8) * NCAT + cb + 1] = acc[mt][nt][3] + b1;
            }
        }
    }
}

// ---------------------------------------------------------------------------
// 1) Fused launch: value-proj GEMM (blocks 0..255) + depthwise conv (rest)
// ---------------------------------------------------------------------------
__global__ void __launch_bounds__(256, 2)
conv_gemm_kernel(const float* __restrict__ in,
                 const float* __restrict__ w_in,
                 const float* __restrict__ b_in,
                 const float* __restrict__ dwk,
                 const float* __restrict__ dwb) {
    __shared__ float smem[SMEM_FLOATS];
    if (blockIdx.x < 256) {
        gemm_body<1, 0, 0>(in, w_in, w_in, b_in, b_in, b_in, b_in, g_xv,
                           blockIdx.x & 1, blockIdx.x >> 1, smem);
        return;
    }
    float (*sp)[66] = (float (*)[66])smem;
    int b = blockIdx.x - 256;
    int n = b >> 8, c = b & 255;
    int tid = threadIdx.x;

    for (int i = tid; i < 66 * 66; i += 256) ((float*)sp)[i] = 0.f;
    __syncthreads();

    const float* src = in + ((size_t)n * CC + c) * HWSZ;
    for (int i = tid; i < HWSZ; i += 256) {
        int h = i >> 6, w = i & 63;
        sp[h + 1][w + 1] = src[i];
    }
    __syncthreads();

    float k00 = dwk[0 * CC + c], k01 = dwk[1 * CC + c], k02 = dwk[2 * CC + c];
    float k10 = dwk[3 * CC + c], k11 = dwk[4 * CC + c], k12 = dwk[5 * CC + c];
    float k20 = dwk[6 * CC + c], k21 = dwk[7 * CC + c], k22 = dwk[8 * CC + c];
    float bb  = dwb[c];

    float* dst = g_c1 + ((size_t)n * CC + c) * HWSZ;
    for (int i = tid; i < HWSZ; i += 256) {
        int h = i >> 6, w = i & 63;
        float acc = bb;
        acc = fmaf(sp[h    ][w    ], k00, acc);
        acc = fmaf(sp[h    ][w + 1], k01, acc);
        acc = fmaf(sp[h    ][w + 2], k02, acc);
        acc = fmaf(sp[h + 1][w    ], k10, acc);
        acc = fmaf(sp[h + 1][w + 1], k11, acc);
        acc = fmaf(sp[h + 1][w + 2], k12, acc);
        acc = fmaf(sp[h + 2][w    ], k20, acc);
        acc = fmaf(sp[h + 2][w + 1], k21, acc);
        acc = fmaf(sp[h + 2][w + 2], k22, acc);
        dst[i] = acc;
    }
}

// om GEMM: A from g_c1 with fused LN+GELU; B = concat [w_off|w_mask|0]
__global__ void __launch_bounds__(256, 2)
gemm_om_kernel(const float* __restrict__ w_off, const float* __restrict__ w_mask,
               const float* __restrict__ b_off, const float* __restrict__ b_mask,
               const float* __restrict__ lng, const float* __restrict__ lnb,
               float* __restrict__ Cout) {
    __shared__ float smem[SMEM_FLOATS];
    gemm_body<2, 2, 0>(g_c1, w_off, w_mask, b_off, b_mask, lng, lnb, Cout,
                       blockIdx.x & 1, blockIdx.x >> 1, smem);
}

__global__ void __launch_bounds__(256, 2)
gemm_out_kernel(const float* __restrict__ A, const float* __restrict__ B,
                const float* __restrict__ bias, float* __restrict__ Cout) {
    __shared__ float smem[SMEM_FLOATS];
    gemm_body<0, 0, 1>(A, B, B, bias, bias, bias, bias, Cout,
                       blockIdx.x & 1, blockIdx.x >> 1, smem);
}

// ---------------------------------------------------------------------------
// 2) LN stats only: per-token mean + rsqrt(var+eps) from NCHW conv output.
// ---------------------------------------------------------------------------
__global__ void __launch_bounds__(256)
ln_stats_kernel() {
    __shared__ float tile[256][33];

    int tid = threadIdx.x;
    int t0 = blockIdx.x * 32;
    int n = t0 >> 12, hw0 = t0 & 4095;

    const float* src = g_c1 + (size_t)n * CC * HWSZ + hw0;
    int tx = tid & 31, ty = tid >> 5;
    #pragma unroll 4
    for (int cc = 0; cc < 32; cc++) {
        int ch = cc * 8 + ty;
        tile[ch][tx] = src[(size_t)ch * HWSZ + tx];
    }
    __syncthreads();

    int tok = tid >> 3, thr = tid & 7;
    float s1 = 0.f, s2 = 0.f;
    #pragma unroll 8
    for (int i = 0; i < 32; i++) {
        float v = tile[thr + 8 * i][tok];
        s1 += v; s2 += v * v;
    }
    #pragma unroll
    for (int d = 1; d < 8; d <<= 1) {
        s1 += __shfl_xor_sync(0xffffffffu, s1, d);
        s2 += __shfl_xor_sync(0xffffffffu, s2, d);
    }
    if (thr == 0) {
        float mu = s1 * (1.0f / 256.0f);
        float var = s2 * (1.0f / 256.0f) - mu * mu;
        g_mu[t0 + tok] = mu;
        g_rs[t0 + tok] = rsqrtf(var + 1e-6f);
    }
}

// ---------------------------------------------------------------------------
// 5+6) DCNv3 sampling + fused softmax — one-phase, ALU-thinned.
//      Int32 base-index + constant-offset addressing (bit-identical math):
//      ib = ((y0-1)*64 + (x0-1))*64; neighbors at +64, +4096, +4160.
// ---------------------------------------------------------------------------
__global__ void __launch_bounds__(256)
dcn_kernel() {
    int tid = threadIdx.x;
    int t   = blockIdx.x * 4 + (tid >> 6);
    int sub = tid & 63;
    int g   = sub >> 3, l8 = sub & 7;
    int n = t >> 12, hw = t & 4095, h = hw >> 6, w = hw & 63;

    const float* off = g_om + (size_t)t * NCAT + g * (PP * 2);
    const float* lg  = g_om + (size_t)t * NCAT + NOFF + g * PP;
    const float4* xvb = (const float4*)(g_xv + (size_t)n * HWSZ * CC + g * CG) + l8;
    // pixel stride in float4 units: CC/4 = 64

    float e[PP];
    float mx = lg[0];
    #pragma unroll
    for (int p = 1; p < PP; p++) mx = fmaxf(mx, lg[p]);
    float s = 0.f;
    #pragma unroll
    for (int p = 0; p < PP; p++) { e[p] = __expf(lg[p] - mx); s += e[p]; }
    float inv = 1.0f / s;

    float ax = 0.f, ay = 0.f, az = 0.f, aw = 0.f;
    #pragma unroll
    for (int p = 0; p < PP; p++) {
        float kx = (float)(p / 3 - 1);
        float ky = (float)(p % 3 - 1);
        float px = (float)w + 1.0f + 2.0f * (kx + off[p * 2 + 0]);
        float py = (float)h + 1.0f + 2.0f * (ky + off[p * 2 + 1]);
        int x0 = __float2int_rd(px);
        int y0 = __float2int_rd(py);
        float wx = px - (float)x0;
        float wy = py - (float)y0;
        float m = e[p] * inv;

        // one-sided unsigned range tests (valid iff in [0,63])
        bool cx0 = (unsigned)(x0 - 1) < (unsigned)WW;
        bool cx1 = (unsigned)x0       < (unsigned)WW;
        bool cy0 = (unsigned)(y0 - 1) < (unsigned)HH;
        bool cy1 = (unsigned)y0       < (unsigned)HH;

        // base index in float4 units; neighbor offsets are exact constants
        int ib = ((y0 - 1) * WW + (x0 - 1)) * (CC / 4);

        float4 v00 = {0,0,0,0}, v01 = {0,0,0,0}, v10 = {0,0,0,0}, v11 = {0,0,0,0};
        if (cx0 & cy0) v00 = xvb[ib];
        if (cx1 & cy0) v01 = xvb[ib + (CC / 4)];
        if (cx0 & cy1) v10 = xvb[ib + WW * (CC / 4)];
        if (cx1 & cy1) v11 = xvb[ib + (WW + 1) * (CC / 4)];

        float w00 = m * (1.f - wx) * (1.f - wy);
        float w01 = m * wx * (1.f - wy);
        float w10 = m * (1.f - wx) * wy;
        float w11 = m * wx * wy;

        ax = fmaf(w00, v00.x, fmaf(w01, v01.x, fmaf(w10, v10.x, fmaf(w11, v11.x, ax))));
        ay = fmaf(w00, v00.y, fmaf(w01, v01.y, fmaf(w10, v10.y, fmaf(w11, v11.y, ay))));
        az = fmaf(w00, v00.z, fmaf(w01, v01.z, fmaf(w10, v10.z, fmaf(w11, v11.z, az))));
        aw = fmaf(w00, v00.w, fmaf(w01, v01.w, fmaf(w10, v10.w, fmaf(w11, v11.w, aw))));
    }
    ((float4*)(g_y + (size_t)t * CC + g * CG))[l8] = make_float4(ax, ay, az, aw);
}

// ---------------------------------------------------------------------------
extern "C" void kernel_launch(void* const* d_in, const int* in_sizes, int n_in,
                              void* d_out, int out_size) {
    const float* inputs = (const float*)d_in[0];
    const float* w_in   = (const float*)d_in[1];
    const float* b_in   = (const float*)d_in[2];
    const float* dw_k   = (const float*)d_in[3];
    const float* dw_b   = (const float*)d_in[4];
    const float* ln_g   = (const float*)d_in[5];
    const float* ln_b   = (const float*)d_in[6];
    const float* w_off  = (const float*)d_in[7];
    const float* b_off  = (const float*)d_in[8];
    const float* w_mask = (const float*)d_in[9];
    const float* b_mask = (const float*)d_in[10];
    const float* w_out  = (const float*)d_in[11];
    const float* b_out  = (const float*)d_in[12];
    float* out = (float*)d_out;

    static float *p_om = nullptr, *p_y = nullptr;
    if (!p_om) {
        cudaGetSymbolAddress((void**)&p_om, g_om);
        cudaGetSymbolAddress((void**)&p_y,  g_y);
    }

    // 1) fused: value-proj GEMM + depthwise conv
    conv_gemm_kernel<<<256 + NB * CC, 256>>>(inputs, w_in, b_in, dw_k, dw_b);
    // 2) LN stats (mean + rsig per token)
    ln_stats_kernel<<<MTOK / 32, 256>>>();
    // 3) offset + mask logits; LN+GELU fused into A staging
    gemm_om_kernel<<<256, 256>>>(w_off, w_mask, b_off, b_mask, ln_g, ln_b, p_om);
    // 4) softmax + deformable sampling (one-phase, ALU-thinned)
    dcn_kernel<<<MTOK / 4, 256>>>();
    // 5) output projection, NCHW store
    gemm_out_kernel<<<256, 256>>>(p_y, w_out, b_out, out);
}